// round 3
// baseline (speedup 1.0000x reference)
#include <cuda_runtime.h>
#include <math.h>

// dims: (1,1,D=160,H=192,W=160), x fastest
#define DW 160
#define DH 192
#define DD 160
#define SLICE (DH*DW)
#define NVOX (DD*SLICE)

#define TX 32
#define TY 8
#define CZ 32
#define SMW (TX+2)
#define SMH (TY+2)
#define NTHREADS (TX*TY)
#define GXD (DW/TX)   // 5
#define GYD (DH/TY)   // 24
#define GZD (DD/CZ)   // 5
#define NBLOCKS (GXD*GYD*GZD)   // 600
#define FEPS 1e-10f

__device__ float g_partial[NBLOCKS];
__device__ unsigned int g_count = 0;

// minimax atan: odd poly on [0,1], reciprocal fold for |x|>1. max err ~2e-6 rad.
__device__ __forceinline__ float fast_atanf(float x)
{
    const float ax = fabsf(x);
    const bool inv = ax > 1.0f;
    const float t = inv ? __fdividef(1.0f, ax) : ax;
    const float z = t * t;
    float p = -0.0117212f;
    p = fmaf(p, z, 0.05265332f);
    p = fmaf(p, z, -0.11643287f);
    p = fmaf(p, z, 0.19354346f);
    p = fmaf(p, z, -0.33262347f);
    p = fmaf(p, z, 0.99997726f);
    p = p * t;
    const float r = inv ? (1.5707963267948966f - p) : p;
    return copysignf(r, x);
}

__global__ __launch_bounds__(NTHREADS, 5)
void demons_kernel(const float* __restrict__ Mp,
                   const float* __restrict__ Sp,
                   const float* __restrict__ Fp,
                   float* __restrict__ out)
{
    __shared__ float2 sm[2][SMH][SMW];      // .x = M, .y = S
    __shared__ float warpred[NTHREADS / 32];
    __shared__ bool isLast;

    const int tx = threadIdx.x, ty = threadIdx.y;
    const int tid = ty * TX + tx;
    const int x = blockIdx.x * TX + tx;
    const int y = blockIdx.y * TY + ty;
    const int zbase = blockIdx.z * CZ;
    const int bid = blockIdx.x + GXD * (blockIdx.y + GYD * blockIdx.z);

    // halo-load mapping (z-invariant): each thread covers <=2 of 340 slots
    const int ly0 = tid / SMW, lx0 = tid - ly0 * SMW;
    const int gy0 = blockIdx.y * TY + ly0 - 1;
    const int gx0 = blockIdx.x * TX + lx0 - 1;
    const bool v0 = (gy0 >= 0) && (gy0 < DH) && (gx0 >= 0) && (gx0 < DW);
    const int off0 = v0 ? (gy0 * DW + gx0) : 0;

    const int i1 = tid + NTHREADS;
    const bool has1 = (i1 < SMH * SMW);
    const int ly1 = has1 ? (i1 / SMW) : 0;
    const int lx1 = has1 ? (i1 - ly1 * SMW) : 0;
    const int gy1 = blockIdx.y * TY + ly1 - 1;
    const int gx1 = blockIdx.x * TX + lx1 - 1;
    const bool v1 = has1 && (gy1 >= 0) && (gy1 < DH) && (gx1 >= 0) && (gx1 < DW);
    const int off1 = v1 ? (gy1 * DW + gx1) : 0;

    // per-slice separable responses, explicit register ring
    // A = smooth_y x diff_x ; B = diff_y x smooth_x ; C = smooth_y x box_x
    float AM0, AM1, AM2, BM0, BM1, BM2, CM0, CM1, CM2, Mc0, Mc1, Mc2;
    float AS0, AS1, AS2, BS0, BS1, BS2, CS0, CS1, CS2, Sc0, Sc1, Sc2;
    AM0=AM1=BM0=BM1=CM0=CM1=Mc0=Mc1=0.f;
    AS0=AS1=BS0=BS1=CS0=CS1=Sc0=Sc1=0.f;
    float acc = 0.f;

    // prefetch slice zbase-1 (iteration j=0)
    float pm0, ps0, pm1, ps1;
    {
        const int s = zbase - 1;
        const bool zin = (s >= 0);
        const int base = s * SLICE;
        pm0 = (zin && v0) ? __ldg(Mp + base + off0) : 0.f;
        ps0 = (zin && v0) ? __ldg(Sp + base + off0) : 0.f;
        pm1 = (zin && v1) ? __ldg(Mp + base + off1) : 0.f;
        ps1 = (zin && v1) ? __ldg(Sp + base + off1) : 0.f;
    }

    #pragma unroll 6
    for (int j = 0; j <= CZ + 1; ++j) {
        const int b = j & 1;

        // commit prefetched slice to smem
        sm[b][ly0][lx0] = make_float2(pm0, ps0);
        if (has1) sm[b][ly1][lx1] = make_float2(pm1, ps1);

        // prefetch next slice (LDGs in flight across sync+compute)
        if (j <= CZ) {
            const int s = zbase + j;
            const bool zin = (s < DD);
            const int base = s * SLICE;
            pm0 = (zin && v0) ? __ldg(Mp + base + off0) : 0.f;
            ps0 = (zin && v0) ? __ldg(Sp + base + off0) : 0.f;
            pm1 = (zin && v1) ? __ldg(Mp + base + off1) : 0.f;
            ps1 = (zin && v1) ? __ldg(Sp + base + off1) : 0.f;
        }
        __syncthreads();

        // in-plane separable responses (float2: M=.x, S=.y)
        const float2 a0 = sm[b][ty + 0][tx], a1 = sm[b][ty + 0][tx + 1], a2 = sm[b][ty + 0][tx + 2];
        const float2 q0 = sm[b][ty + 1][tx], q1 = sm[b][ty + 1][tx + 1], q2 = sm[b][ty + 1][tx + 2];
        const float2 c0 = sm[b][ty + 2][tx], c1 = sm[b][ty + 2][tx + 1], c2 = sm[b][ty + 2][tx + 2];

        {   // M
            const float rD0 = a2.x - a0.x, rSm0 = fmaf(2.f, a1.x, a0.x + a2.x), rB0 = a0.x + a1.x + a2.x;
            const float rD1 = q2.x - q0.x, rSm1 = fmaf(2.f, q1.x, q0.x + q2.x), rB1 = q0.x + q1.x + q2.x;
            const float rD2 = c2.x - c0.x, rSm2 = fmaf(2.f, c1.x, c0.x + c2.x), rB2 = c0.x + c1.x + c2.x;
            AM2 = fmaf(2.f, rD1, rD0 + rD2);
            BM2 = rSm2 - rSm0;
            CM2 = fmaf(2.f, rB1, rB0 + rB2);
            Mc2 = q1.x;
            (void)rSm1;
        }
        {   // S
            const float rD0 = a2.y - a0.y, rSm0 = fmaf(2.f, a1.y, a0.y + a2.y), rB0 = a0.y + a1.y + a2.y;
            const float rD1 = q2.y - q0.y, rSm1 = fmaf(2.f, q1.y, q0.y + q2.y), rB1 = q0.y + q1.y + q2.y;
            const float rD2 = c2.y - c0.y, rSm2 = fmaf(2.f, c1.y, c0.y + c2.y), rB2 = c0.y + c1.y + c2.y;
            AS2 = fmaf(2.f, rD1, rD0 + rD2);
            BS2 = rSm2 - rSm0;
            CS2 = fmaf(2.f, rB1, rB0 + rB2);
            Sc2 = q1.y;
            (void)rSm1;
        }

        // emit output voxel z = zbase + j - 2 once three slices are live
        if (j >= 2) {
            const int z = zbase + j - 2;

            const float Mx = AM0 + AM1 + AM2;
            const float My = BM0 + BM1 + BM2;
            const float Mz = CM2 - CM0;
            const float Sx = AS0 + AS1 + AS2;
            const float Sy = BS0 + BS1 + BS2;
            const float Sz = CS2 - CS0;

            const float Id  = Mc1 - Sc1;
            const float Id2 = fmaf(Id, Id, FEPS);
            const float dS = fmaf(Sx, Sx, fmaf(Sy, Sy, fmaf(Sz, Sz, Id2)));
            const float dM = fmaf(Mx, Mx, fmaf(My, My, fmaf(Mz, Mz, Id2)));
            const float invS = __fdividef(1.f, dS);
            const float invM = __fdividef(1.f, dM);
            const float Ux = Id * fmaf(Sx, invS, Mx * invM);
            const float Uy = Id * fmaf(Sy, invS, My * invM);
            const float Uz = Id * fmaf(Sz, invS, Mz * invM);

            const float izd = __fdividef(1.f, Uz + FEPS);
            const float dxz = fast_atanf(Ux * izd);
            const float dyz = fast_atanf(Uy * izd);

            const int idx = (z * DH + y) * DW + x;
            const float fx = __ldg(Fp + idx);
            const float fy = __ldg(Fp + NVOX + idx);
            const float fz = __ldg(Fp + 2 * NVOX + idx);
            const float ifz = __fdividef(1.f, fz + FEPS);
            const float fxz = fast_atanf(fx * ifz);
            const float fyz = fast_atanf(fy * ifz);

            const float e1 = fxz - dxz;
            const float e2 = fyz - dyz;
            acc = fmaf(e1, e1, acc);
            acc = fmaf(e2, e2, acc);
        }

        // shift register rings (elided by renaming under unroll 6)
        AM0 = AM1; AM1 = AM2;  BM0 = BM1; BM1 = BM2;
        CM0 = CM1; CM1 = CM2;  Mc0 = Mc1; Mc1 = Mc2;
        AS0 = AS1; AS1 = AS2;  BS0 = BS1; BS1 = BS2;
        CS0 = CS1; CS1 = CS2;  Sc0 = Sc1; Sc1 = Sc2;
    }

    // block reduction: warp shuffle + smem
    #pragma unroll
    for (int o = 16; o > 0; o >>= 1) acc += __shfl_xor_sync(0xffffffffu, acc, o);
    if ((tid & 31) == 0) warpred[tid >> 5] = acc;
    __syncthreads();
    if (tid == 0) {
        float v = 0.f;
        #pragma unroll
        for (int w = 0; w < NTHREADS / 32; ++w) v += warpred[w];
        g_partial[bid] = v;
        __threadfence();
        const unsigned int c = atomicAdd(&g_count, 1u);
        isLast = (c == (unsigned)(NBLOCKS - 1));
    }
    __syncthreads();

    // last block reduces 600 partials, writes scalar, resets counter
    if (isLast) {
        float s = 0.f;
        for (int i = tid; i < NBLOCKS; i += NTHREADS) s += g_partial[i];
        #pragma unroll
        for (int o = 16; o > 0; o >>= 1) s += __shfl_xor_sync(0xffffffffu, s, o);
        if ((tid & 31) == 0) warpred[tid >> 5] = s;
        __syncthreads();
        if (tid == 0) {
            float t = 0.f;
            #pragma unroll
            for (int w = 0; w < NTHREADS / 32; ++w) t += warpred[w];
            out[0] = t / (float)NVOX;
            g_count = 0u;
        }
    }
}

extern "C" void kernel_launch(void* const* d_in, const int* in_sizes, int n_in,
                              void* d_out, int out_size)
{
    const float* Mp = (const float*)d_in[0];
    const float* Sp = (const float*)d_in[1];
    const float* Fp = (const float*)d_in[2];
    float* out = (float*)d_out;

    dim3 grid(GXD, GYD, GZD);   // (5, 24, 5) = 600 blocks
    dim3 block(TX, TY, 1);      // (32, 8)
    demons_kernel<<<grid, block>>>(Mp, Sp, Fp, out);
}

// round 4
// speedup vs baseline: 1.0756x; 1.0756x over previous
#include <cuda_runtime.h>
#include <math.h>

// dims: (1,1,D=160,H=192,W=160), x fastest
#define DW 160
#define DH 192
#define DD 160
#define SLICE (DH*DW)
#define NVOX (DD*SLICE)

#define TX 32
#define TY 8
#define CZ 16
#define SMW (TX+2)
#define SMH (TY+2)
#define NTHREADS (TX*TY)
#define GXD (DW/TX)   // 5
#define GYD (DH/TY)   // 24
#define GZD (DD/CZ)   // 10
#define NBLOCKS (GXD*GYD*GZD)   // 1200
#define FEPS 1e-10f

__device__ float g_partial[NBLOCKS];
__device__ unsigned int g_count = 0;

// minimax atan: odd poly on [0,1], reciprocal fold for |x|>1. max err ~2e-6 rad.
__device__ __forceinline__ float fast_atanf(float x)
{
    const float ax = fabsf(x);
    const bool inv = ax > 1.0f;
    const float t = inv ? __fdividef(1.0f, ax) : ax;
    const float z = t * t;
    float p = -0.0117212f;
    p = fmaf(p, z, 0.05265332f);
    p = fmaf(p, z, -0.11643287f);
    p = fmaf(p, z, 0.19354346f);
    p = fmaf(p, z, -0.33262347f);
    p = fmaf(p, z, 0.99997726f);
    p = p * t;
    const float r = inv ? (1.5707963267948966f - p) : p;
    return copysignf(r, x);
}

__global__ __launch_bounds__(NTHREADS, 4)
void demons_kernel(const float* __restrict__ Mp,
                   const float* __restrict__ Sp,
                   const float* __restrict__ Fp,
                   float* __restrict__ out)
{
    __shared__ float2 sm[2][SMH][SMW];      // .x = M, .y = S
    __shared__ float warpred[NTHREADS / 32];
    __shared__ bool isLast;

    const int tx = threadIdx.x, ty = threadIdx.y;
    const int tid = ty * TX + tx;
    const int x = blockIdx.x * TX + tx;
    const int y = blockIdx.y * TY + ty;
    const int zbase = blockIdx.z * CZ;
    const int bid = blockIdx.x + GXD * (blockIdx.y + GYD * blockIdx.z);

    // halo-load mapping (z-invariant): each thread covers <=2 of 340 slots
    const int ly0 = tid / SMW, lx0 = tid - ly0 * SMW;
    const int gy0 = blockIdx.y * TY + ly0 - 1;
    const int gx0 = blockIdx.x * TX + lx0 - 1;
    const bool v0 = (gy0 >= 0) && (gy0 < DH) && (gx0 >= 0) && (gx0 < DW);
    const int off0 = v0 ? (gy0 * DW + gx0) : 0;

    const int i1 = tid + NTHREADS;
    const bool has1 = (i1 < SMH * SMW);
    const int ly1 = has1 ? (i1 / SMW) : 0;
    const int lx1 = has1 ? (i1 - ly1 * SMW) : 0;
    const int gy1 = blockIdx.y * TY + ly1 - 1;
    const int gx1 = blockIdx.x * TX + lx1 - 1;
    const bool v1 = has1 && (gy1 >= 0) && (gy1 < DH) && (gx1 >= 0) && (gx1 < DW);
    const int off1 = v1 ? (gy1 * DW + gx1) : 0;

    // per-slice separable responses, register ring of 3
    // A = smooth_y x diff_x ; B = diff_y x smooth_x ; C = smooth_y x box_x
    float AM0, AM1, AM2, BM0, BM1, BM2, CM0, CM1, CM2, Mc0, Mc1, Mc2;
    float AS0, AS1, AS2, BS0, BS1, BS2, CS0, CS1, CS2, Sc0, Sc1, Sc2;
    AM0=AM1=BM0=BM1=CM0=CM1=Mc0=Mc1=0.f;
    AS0=AS1=BS0=BS1=CS0=CS1=Sc0=Sc1=0.f;
    float acc = 0.f;

    // depth-2 software pipeline: P0 = slice to commit this iter, P1 = next
    float Pm0, Ps0, Pm1, Ps1;    // set P0 (slots 0,1 of halo)
    float Qm0, Qs0, Qm1, Qs1;    // set P1
    {
        const int s = zbase - 1;            // always >= -1; zbase==0 -> pad
        const bool zin = (s >= 0);
        const int base = s * SLICE;
        Pm0 = (zin && v0) ? __ldg(Mp + base + off0) : 0.f;
        Ps0 = (zin && v0) ? __ldg(Sp + base + off0) : 0.f;
        Pm1 = (zin && v1) ? __ldg(Mp + base + off1) : 0.f;
        Ps1 = (zin && v1) ? __ldg(Sp + base + off1) : 0.f;
    }
    {
        const int s = zbase;                // always valid
        const int base = s * SLICE;
        Qm0 = v0 ? __ldg(Mp + base + off0) : 0.f;
        Qs0 = v0 ? __ldg(Sp + base + off0) : 0.f;
        Qm1 = v1 ? __ldg(Mp + base + off1) : 0.f;
        Qs1 = v1 ? __ldg(Sp + base + off1) : 0.f;
    }

    #pragma unroll 2
    for (int j = 0; j <= CZ + 1; ++j) {
        const int b = j & 1;

        // commit slice (zbase-1+j) to smem
        sm[b][ly0][lx0] = make_float2(Pm0, Ps0);
        if (has1) sm[b][ly1][lx1] = make_float2(Pm1, Ps1);

        // rotate pipeline and issue load for slice zbase+j+1 (2 iters ahead of use)
        Pm0 = Qm0; Ps0 = Qs0; Pm1 = Qm1; Ps1 = Qs1;
        if (j <= CZ - 1) {
            const int s = zbase + j + 1;
            const bool zin = (s < DD);
            const int base = s * SLICE;
            Qm0 = (zin && v0) ? __ldg(Mp + base + off0) : 0.f;
            Qs0 = (zin && v0) ? __ldg(Sp + base + off0) : 0.f;
            Qm1 = (zin && v1) ? __ldg(Mp + base + off1) : 0.f;
            Qs1 = (zin && v1) ? __ldg(Sp + base + off1) : 0.f;
        }
        __syncthreads();

        // in-plane separable responses (float2: M=.x, S=.y)
        const float2 a0 = sm[b][ty + 0][tx], a1 = sm[b][ty + 0][tx + 1], a2 = sm[b][ty + 0][tx + 2];
        const float2 q0 = sm[b][ty + 1][tx], q1 = sm[b][ty + 1][tx + 1], q2 = sm[b][ty + 1][tx + 2];
        const float2 c0 = sm[b][ty + 2][tx], c1 = sm[b][ty + 2][tx + 1], c2 = sm[b][ty + 2][tx + 2];

        {   // M
            const float rD0 = a2.x - a0.x, rSm0 = fmaf(2.f, a1.x, a0.x + a2.x), rB0 = a0.x + a1.x + a2.x;
            const float rD1 = q2.x - q0.x,                                      rB1 = q0.x + q1.x + q2.x;
            const float rD2 = c2.x - c0.x, rSm2 = fmaf(2.f, c1.x, c0.x + c2.x), rB2 = c0.x + c1.x + c2.x;
            AM2 = fmaf(2.f, rD1, rD0 + rD2);
            BM2 = rSm2 - rSm0;
            CM2 = fmaf(2.f, rB1, rB0 + rB2);
            Mc2 = q1.x;
        }
        {   // S
            const float rD0 = a2.y - a0.y, rSm0 = fmaf(2.f, a1.y, a0.y + a2.y), rB0 = a0.y + a1.y + a2.y;
            const float rD1 = q2.y - q0.y,                                      rB1 = q0.y + q1.y + q2.y;
            const float rD2 = c2.y - c0.y, rSm2 = fmaf(2.f, c1.y, c0.y + c2.y), rB2 = c0.y + c1.y + c2.y;
            AS2 = fmaf(2.f, rD1, rD0 + rD2);
            BS2 = rSm2 - rSm0;
            CS2 = fmaf(2.f, rB1, rB0 + rB2);
            Sc2 = q1.y;
        }

        // emit output voxel z = zbase + j - 2 once three slices are live
        if (j >= 2) {
            const int z = zbase + j - 2;

            const float Mx = AM0 + AM1 + AM2;
            const float My = BM0 + BM1 + BM2;
            const float Mz = CM2 - CM0;
            const float Sx = AS0 + AS1 + AS2;
            const float Sy = BS0 + BS1 + BS2;
            const float Sz = CS2 - CS0;

            const float Id  = Mc1 - Sc1;
            const float Id2 = fmaf(Id, Id, FEPS);
            const float dS = fmaf(Sx, Sx, fmaf(Sy, Sy, fmaf(Sz, Sz, Id2)));
            const float dM = fmaf(Mx, Mx, fmaf(My, My, fmaf(Mz, Mz, Id2)));
            const float invS = __fdividef(1.f, dS);
            const float invM = __fdividef(1.f, dM);
            const float Ux = Id * fmaf(Sx, invS, Mx * invM);
            const float Uy = Id * fmaf(Sy, invS, My * invM);
            const float Uz = Id * fmaf(Sz, invS, Mz * invM);

            const float izd = __fdividef(1.f, Uz + FEPS);
            const float dxz = fast_atanf(Ux * izd);
            const float dyz = fast_atanf(Uy * izd);

            const int idx = (z * DH + y) * DW + x;
            const float fx = __ldg(Fp + idx);
            const float fy = __ldg(Fp + NVOX + idx);
            const float fz = __ldg(Fp + 2 * NVOX + idx);
            const float ifz = __fdividef(1.f, fz + FEPS);
            const float fxz = fast_atanf(fx * ifz);
            const float fyz = fast_atanf(fy * ifz);

            const float e1 = fxz - dxz;
            const float e2 = fyz - dyz;
            acc = fmaf(e1, e1, acc);
            acc = fmaf(e2, e2, acc);
        }

        // shift register rings
        AM0 = AM1; AM1 = AM2;  BM0 = BM1; BM1 = BM2;
        CM0 = CM1; CM1 = CM2;  Mc0 = Mc1; Mc1 = Mc2;
        AS0 = AS1; AS1 = AS2;  BS0 = BS1; BS1 = BS2;
        CS0 = CS1; CS1 = CS2;  Sc0 = Sc1; Sc1 = Sc2;
    }

    // block reduction: warp shuffle + smem
    #pragma unroll
    for (int o = 16; o > 0; o >>= 1) acc += __shfl_xor_sync(0xffffffffu, acc, o);
    if ((tid & 31) == 0) warpred[tid >> 5] = acc;
    __syncthreads();
    if (tid == 0) {
        float v = 0.f;
        #pragma unroll
        for (int w = 0; w < NTHREADS / 32; ++w) v += warpred[w];
        g_partial[bid] = v;
        __threadfence();
        const unsigned int c = atomicAdd(&g_count, 1u);
        isLast = (c == (unsigned)(NBLOCKS - 1));
    }
    __syncthreads();

    // last block reduces partials, writes scalar, resets counter
    if (isLast) {
        float s = 0.f;
        for (int i = tid; i < NBLOCKS; i += NTHREADS) s += g_partial[i];
        #pragma unroll
        for (int o = 16; o > 0; o >>= 1) s += __shfl_xor_sync(0xffffffffu, s, o);
        if ((tid & 31) == 0) warpred[tid >> 5] = s;
        __syncthreads();
        if (tid == 0) {
            float t = 0.f;
            #pragma unroll
            for (int w = 0; w < NTHREADS / 32; ++w) t += warpred[w];
            out[0] = t / (float)NVOX;
            g_count = 0u;
        }
    }
}

extern "C" void kernel_launch(void* const* d_in, const int* in_sizes, int n_in,
                              void* d_out, int out_size)
{
    const float* Mp = (const float*)d_in[0];
    const float* Sp = (const float*)d_in[1];
    const float* Fp = (const float*)d_in[2];
    float* out = (float*)d_out;

    dim3 grid(GXD, GYD, GZD);   // (5, 24, 10) = 1200 blocks
    dim3 block(TX, TY, 1);      // (32, 8)
    demons_kernel<<<grid, block>>>(Mp, Sp, Fp, out);
}